// round 8
// baseline (speedup 1.0000x reference)
#include <cuda_runtime.h>
#include <math.h>
#include <stdint.h>

#define BATCH 32
#define NPTS  512
#define NN    (BATCH*NPTS)     // 16384
#define ND    128
#define F0D   384
#define CATD  1152
#define HROWS 513

// ---------------- scratch (device globals) ----------------
__device__ float g_L  [(size_t)BATCH*NPTS*NPTS];
__device__ float g_G  [(size_t)NN*CATD];           // [F0|F0^2|F0^3] row-major
__device__ float g_Gt [(size_t)BATCH*CATD*NPTS];   // per batch [feat][point]
__device__ float g_LG [(size_t)NN*CATD];
__device__ float g_LGt[(size_t)BATCH*CATD*NPTS];   // LG transposed per batch
__device__ float g_LLG[(size_t)NN*CATD];
__device__ float g_F1 [(size_t)NN*F0D];
__device__ float g_WgT[(size_t)3*ND*CATD];
__device__ float g_WFT[(size_t)ND*F0D];            // scale-folded WF^T
__device__ float g_X  [NN*3];
__device__ float g_deg[NN];
__device__ float g_bnsum[F0D];
__device__ float g_bnsq [F0D];
__device__ float g_colbias[ND];
__device__ unsigned g_dlmax_bits;
__device__ unsigned g_amax_bits;

// ---------------- helpers ----------------
__device__ __forceinline__ uint32_t f2tf(float f) {
    uint32_t u; asm("cvt.rna.tf32.f32 %0, %1;" : "=r"(u) : "f"(f)); return u;
}
#define MMA88(D, A, B) \
    asm volatile("mma.sync.aligned.m16n8k8.row.col.f32.tf32.tf32.f32 " \
        "{%0,%1,%2,%3},{%4,%5,%6,%7},{%8,%9},{%0,%1,%2,%3};" \
        : "+f"((D)[0]), "+f"((D)[1]), "+f"((D)[2]), "+f"((D)[3]) \
        : "r"((A)[0]), "r"((A)[1]), "r"((A)[2]), "r"((A)[3]), \
          "r"((B)[0]), "r"((B)[1]))

// ---------------- small kernels (proven) ----------------
__global__ void init_k() {
    if (threadIdx.x == 0) { g_dlmax_bits = 0u; g_amax_bits = 0u; }
}
__global__ void dlmax_k(const float* __restrict__ dl) {
    int i = blockIdx.x * blockDim.x + threadIdx.x;
    float v = dl[i];
    #pragma unroll
    for (int o = 16; o; o >>= 1) v = fmaxf(v, __shfl_xor_sync(0xffffffff, v, o));
    if ((threadIdx.x & 31) == 0) atomicMax(&g_dlmax_bits, __float_as_uint(v));
}
__global__ void x_k(const float* __restrict__ loc, const float* __restrict__ dl) {
    int i = blockIdx.x * blockDim.x + threadIdx.x;
    if (i >= NN) return;
    float inv = 1.0f / __uint_as_float(g_dlmax_bits);
    g_X[i*3+0] = loc[i*2+0];
    g_X[i*3+1] = loc[i*2+1];
    g_X[i*3+2] = dl[i] * inv;
}
__global__ void a_k() {
    int b  = blockIdx.z;
    int i0 = blockIdx.y * 32, j0 = blockIdx.x * 32;
    __shared__ float Xi[32][3], Xj[32][3];
    int t = threadIdx.x;
    if (t < 96)       ((float*)Xi)[t]    = g_X[((size_t)b*NPTS + i0)*3 + t];
    else if (t < 192) ((float*)Xj)[t-96] = g_X[((size_t)b*NPTS + j0)*3 + (t-96)];
    __syncthreads();
    int tx = t & 31, ty = t >> 5;
    float xj0 = Xj[tx][0], xj1 = Xj[tx][1], xj2 = Xj[tx][2];
    float m = 0.0f;
    float* Ab = g_L + (size_t)b * NPTS * NPTS;
    #pragma unroll
    for (int r = 0; r < 4; r++) {
        int i = ty * 4 + r;
        float dx = Xi[i][0]-xj0, dy = Xi[i][1]-xj1, dz = Xi[i][2]-xj2;
        float d2 = dx*dx + dy*dy + dz*dz;
        float v  = (i0 + i == j0 + tx) ? 0.0f : rsqrtf(d2);
        Ab[(size_t)(i0+i)*NPTS + j0 + tx] = v;
        m = fmaxf(m, v);
    }
    #pragma unroll
    for (int o = 16; o; o >>= 1) m = fmaxf(m, __shfl_xor_sync(0xffffffff, m, o));
    __shared__ float wm[8];
    if (tx == 0) wm[ty] = m;
    __syncthreads();
    if (t == 0) {
        float mm = wm[0];
        #pragma unroll
        for (int w = 1; w < 8; w++) mm = fmaxf(mm, wm[w]);
        atomicMax(&g_amax_bits, __float_as_uint(mm));
    }
}
__global__ void deg_k() {
    int gw   = (blockIdx.x * blockDim.x + threadIdx.x) >> 5;
    int lane = threadIdx.x & 31;
    if (gw >= NN) return;
    const float4* row = (const float4*)(g_L + (size_t)gw * NPTS);
    float s = 0.0f;
    #pragma unroll
    for (int w = 0; w < 4; w++) { float4 v = row[lane + w*32]; s += v.x+v.y+v.z+v.w; }
    #pragma unroll
    for (int o = 16; o; o >>= 1) s += __shfl_xor_sync(0xffffffff, s, o);
    if (lane == 0) g_deg[gw] = s / __uint_as_float(g_amax_bits) - 1.0f;
}
__global__ void l_k() {
    size_t idx = (size_t)blockIdx.x * blockDim.x + threadIdx.x;
    if (idx >= (size_t)BATCH*NPTS*NPTS) return;
    float inv = 1.0f / __uint_as_float(g_amax_bits);
    int    j  = (int)(idx & 511);
    size_t r  = idx >> 9;
    int    i  = (int)(r & 511);
    float v = -g_L[idx] * inv;
    if (i == j) v += g_deg[r];
    g_L[idx] = v;
}
__global__ void g0_k(const float* __restrict__ Wi, const float* __restrict__ bi) {
    int t = blockIdx.x * blockDim.x + threadIdx.x;
    if (t >= NN * F0D) return;
    int row = t / F0D, j = t - row * F0D;
    const float* x = &g_X[row*3];
    float f = fmaf(x[0], Wi[j], fmaf(x[1], Wi[F0D+j], fmaf(x[2], Wi[2*F0D+j], bi[j])));
    size_t base = (size_t)row * CATD;
    g_G[base + j]         = f;
    g_G[base + F0D + j]   = f*f;
    g_G[base + 2*F0D + j] = f*f*f;
}
__global__ void g0t_k(const float* __restrict__ Wi, const float* __restrict__ bi) {
    int idx = blockIdx.x * blockDim.x + threadIdx.x;
    if (idx >= NN * F0D) return;
    int n = idx & 511;
    int rest = idx >> 9;
    int j = rest % F0D, b = rest / F0D;
    const float* x = &g_X[((size_t)b*NPTS + n)*3];
    float f = fmaf(x[0], Wi[j], fmaf(x[1], Wi[F0D+j], fmaf(x[2], Wi[2*F0D+j], bi[j])));
    size_t base = (size_t)b*CATD*NPTS + (size_t)j*NPTS + n;
    g_Gt[base]                      = f;
    g_Gt[base + (size_t)F0D*NPTS]   = f*f;
    g_Gt[base + (size_t)2*F0D*NPTS] = f*f*f;
}
__global__ void wgt_k(const float* __restrict__ W1, const float* __restrict__ W2,
                      const float* __restrict__ W3) {
    int kb = blockIdx.y, j = blockIdx.x;
    const float* W = (kb == 0) ? W1 : (kb == 1 ? W2 : W3);
    float* dst = g_WgT + ((size_t)kb*ND + j)*CATD;
    for (int k = threadIdx.x; k < CATD; k += blockDim.x) dst[k] = W[(size_t)k*ND + j];
}

// ---------------- unified mma.sync tf32 GEMM ----------------
// C[m][n] = sum_k A[m][k] * B[n][k].  CTA tile 128x128, 8 warps (2Mx4N), K chunk 32.
// SPLIT: 3xTF32 (hi/lo) for fp32-class accuracy.
#define ASTRIDE 36
#define STG_FLOATS (128*ASTRIDE)          // per matrix per stage
#define SMEM_MMA (2 * 2 * STG_FLOATS * 4) // 73728 B

template<int MODE, bool SPLIT>
__global__ void __launch_bounds__(256) mma_k(
    const float* __restrict__ b1, const float* __restrict__ b2,
    const float* __restrict__ b3, float* __restrict__ outp)
{
    extern __shared__ float sm[];
    int tid = threadIdx.x, lane = tid & 31, wid = tid >> 5;
    int wM = wid >> 2, wN = wid & 3;       // 2 x 4 warp grid

    int bm = 0, bn = 0, z = 0, kb = 0;
    constexpr int NCH = (MODE <= 2) ? 16 : (MODE == 3 ? 36 : 12);
    const float* Bbase = nullptr;
    int ldb = 0;
    if constexpr (MODE == 1) {             // LG = L @ G
        z = blockIdx.z; bm = blockIdx.y*128; bn = blockIdx.x*128;
        Bbase = g_Gt + (size_t)z*CATD*NPTS; ldb = NPTS;
    } else if constexpr (MODE == 2) {      // LLG = L @ LG
        z = blockIdx.z; bm = blockIdx.y*128; bn = blockIdx.x*128;
        Bbase = g_LGt + (size_t)z*CATD*NPTS; ldb = NPTS;
    } else if constexpr (MODE == 3) {      // F1 block kb
        bm = blockIdx.x*128; kb = blockIdx.y;
        Bbase = g_WgT + (size_t)kb*ND*CATD; ldb = CATD;
    } else {                               // final
        bm = blockIdx.x*128;
        Bbase = g_WFT; ldb = F0D;
    }

    // per-thread gmem<->smem geometry: 4 float4 per matrix per stage
    int rowi[4], c4i[4];
    #pragma unroll
    for (int i = 0; i < 4; i++) {
        int idx = tid + i*256;
        rowi[i] = idx >> 3; c4i[i] = idx & 7;
    }

    float4 pa[4], pb[4];
    auto load_chunk = [&](int c) {
        #pragma unroll
        for (int i = 0; i < 4; i++) {
            const float* ap;
            if constexpr (MODE == 1 || MODE == 2) {
                ap = g_L + (size_t)z*NPTS*NPTS + (size_t)(bm + rowi[i])*NPTS + c*32 + c4i[i]*4;
            } else if constexpr (MODE == 3) {
                int p = c / 12, rem = c - p*12;
                const float* src = (p == 0) ? g_G : (p == 1 ? g_LG : g_LLG);
                ap = src + (size_t)(bm + rowi[i])*CATD + kb*F0D + rem*32 + c4i[i]*4;
            } else {
                ap = g_F1 + (size_t)(bm + rowi[i])*F0D + c*32 + c4i[i]*4;
            }
            pa[i] = *(const float4*)ap;
            pb[i] = *(const float4*)(Bbase + (size_t)(bn + rowi[i])*ldb + c*32 + c4i[i]*4);
        }
    };
    auto store_stage = [&](int s) {
        float* As = sm + s * 2 * STG_FLOATS;
        float* Bs = As + STG_FLOATS;
        #pragma unroll
        for (int i = 0; i < 4; i++) {
            *(float4*)&As[rowi[i]*ASTRIDE + c4i[i]*4] = pa[i];
            *(float4*)&Bs[rowi[i]*ASTRIDE + c4i[i]*4] = pb[i];
        }
    };

    float acc[4][4][4];
    #pragma unroll
    for (int a = 0; a < 4; a++)
        #pragma unroll
        for (int b = 0; b < 4; b++)
            #pragma unroll
            for (int q = 0; q < 4; q++) acc[a][b][q] = 0.0f;

    load_chunk(0);
    store_stage(0);
    __syncthreads();

    #pragma unroll 1
    for (int c = 0; c < NCH; c++) {
        if (c + 1 < NCH) load_chunk(c + 1);
        const float* As = sm + (c & 1) * 2 * STG_FLOATS;
        const float* Bs = As + STG_FLOATS;
        #pragma unroll
        for (int ks = 0; ks < 4; ks++) {
            uint32_t ah[4][4], al[4][4], bh[4][2], bl[4][2];
            #pragma unroll
            for (int mt = 0; mt < 4; mt++) {
                int r = wM*64 + mt*16 + (lane >> 2);
                int k = ks*8 + (lane & 3);
                float a0 = As[r*ASTRIDE + k],     a1 = As[(r+8)*ASTRIDE + k];
                float a2 = As[r*ASTRIDE + k + 4], a3 = As[(r+8)*ASTRIDE + k + 4];
                ah[mt][0] = f2tf(a0); ah[mt][1] = f2tf(a1);
                ah[mt][2] = f2tf(a2); ah[mt][3] = f2tf(a3);
                if (SPLIT) {
                    al[mt][0] = f2tf(a0 - __uint_as_float(ah[mt][0]));
                    al[mt][1] = f2tf(a1 - __uint_as_float(ah[mt][1]));
                    al[mt][2] = f2tf(a2 - __uint_as_float(ah[mt][2]));
                    al[mt][3] = f2tf(a3 - __uint_as_float(ah[mt][3]));
                }
            }
            #pragma unroll
            for (int nt = 0; nt < 4; nt++) {
                int n = wN*32 + nt*8 + (lane >> 2);
                int k = ks*8 + (lane & 3);
                float b0 = Bs[n*ASTRIDE + k], bq = Bs[n*ASTRIDE + k + 4];
                bh[nt][0] = f2tf(b0); bh[nt][1] = f2tf(bq);
                if (SPLIT) {
                    bl[nt][0] = f2tf(b0 - __uint_as_float(bh[nt][0]));
                    bl[nt][1] = f2tf(bq - __uint_as_float(bh[nt][1]));
                }
            }
            #pragma unroll
            for (int mt = 0; mt < 4; mt++)
                #pragma unroll
                for (int nt = 0; nt < 4; nt++) {
                    MMA88(acc[mt][nt], ah[mt], bh[nt]);
                    if (SPLIT) {
                        MMA88(acc[mt][nt], al[mt], bh[nt]);
                        MMA88(acc[mt][nt], ah[mt], bl[nt]);
                    }
                }
        }
        if (c + 1 < NCH) {
            __syncthreads();
            store_stage((c + 1) & 1);
            __syncthreads();
        }
    }

    // ---------------- epilogue ----------------
    #pragma unroll
    for (int mt = 0; mt < 4; mt++) {
        #pragma unroll
        for (int nt = 0; nt < 4; nt++) {
            int r0 = bm + wM*64 + mt*16 + (lane >> 2);
            int c0 = bn + wN*32 + nt*8 + 2*(lane & 3);
            float* d = acc[mt][nt];
            if constexpr (MODE == 1) {
                float* C  = g_LG  + (size_t)z*NPTS*CATD;
                float* Ct = g_LGt + (size_t)z*CATD*NPTS;
                C[(size_t)r0*CATD + c0]       = d[0];
                C[(size_t)r0*CATD + c0 + 1]   = d[1];
                C[(size_t)(r0+8)*CATD + c0]   = d[2];
                C[(size_t)(r0+8)*CATD + c0+1] = d[3];
                Ct[(size_t)c0*NPTS + r0]       = d[0];
                Ct[(size_t)(c0+1)*NPTS + r0]   = d[1];
                Ct[(size_t)c0*NPTS + r0 + 8]   = d[2];
                Ct[(size_t)(c0+1)*NPTS + r0+8] = d[3];
            } else if constexpr (MODE == 2) {
                float* C = g_LLG + (size_t)z*NPTS*CATD;
                C[(size_t)r0*CATD + c0]       = d[0];
                C[(size_t)r0*CATD + c0 + 1]   = d[1];
                C[(size_t)(r0+8)*CATD + c0]   = d[2];
                C[(size_t)(r0+8)*CATD + c0+1] = d[3];
            } else if constexpr (MODE == 3) {
                const float* bg = (kb == 0) ? b1 : (kb == 1 ? b2 : b3);
                #pragma unroll
                for (int q = 0; q < 4; q++) {
                    int r = r0 + (q >> 1) * 8;
                    int cc = c0 + (q & 1);
                    float v = d[q] + bg[cc];
                    v = (v > 0.0f) ? v : 0.01f * v;
                    v += g_G[(size_t)r*CATD + kb*128 + cc];
                    g_F1[(size_t)r*F0D + kb*128 + cc] = v;
                }
            } else {
                #pragma unroll
                for (int q = 0; q < 4; q++) {
                    int r = r0 + (q >> 1) * 8;
                    int cc = c0 + (q & 1);
                    int b = r >> 9, n = r & 511;
                    float v = d[q] + g_colbias[cc];
                    outp[((size_t)b*HROWS + 1 + n)*ND + cc] = (v > 0.0f) ? v : 0.01f * v;
                }
            }
        }
    }
}

// ---------------- BN stats (proven) ----------------
__global__ void bnstat_k() {
    int c = blockIdx.x, t = threadIdx.x;
    float s = 0.0f, q = 0.0f;
    for (int r = t; r < NN; r += 256) {
        float v = g_F1[(size_t)r * F0D + c];
        s += v; q += v * v;
    }
    __shared__ float sh[256], sh2[256];
    sh[t] = s; sh2[t] = q; __syncthreads();
    for (int o = 128; o; o >>= 1) {
        if (t < o) { sh[t] += sh[t+o]; sh2[t] += sh2[t+o]; }
        __syncthreads();
    }
    if (t == 0) { g_bnsum[c] = sh[0]; g_bnsq[c] = sh2[0]; }
}
__global__ void bnfin_k(const float* __restrict__ gamma, const float* __restrict__ beta,
                        const float* __restrict__ WF,    const float* __restrict__ bF) {
    __shared__ float sh[F0D];
    int t = threadIdx.x;                               // 384 threads
    float mu  = g_bnsum[t] * (1.0f / NN);
    float var = g_bnsq[t]  * (1.0f / NN) - mu * mu;
    float sc  = gamma[t] * rsqrtf(var + 1e-5f);
    sh[t]     = beta[t] - mu * sc;
    __syncthreads();
    if (t < ND) {
        float s = bF[t];
        for (int k = 0; k < F0D; k++) s = fmaf(sh[k], WF[(size_t)k*ND + t], s);
        g_colbias[t] = s;
    }
    for (int j = 0; j < ND; j++)
        g_WFT[(size_t)j*F0D + t] = WF[(size_t)t*ND + j] * sc;   // fold BN scale into B
}
__global__ void dep_k(const float* __restrict__ depot, const float* __restrict__ Wd,
                      const float* __restrict__ bd, float* __restrict__ out) {
    int b = blockIdx.x, t = threadIdx.x;
    out[(size_t)b * HROWS * ND + t] =
        fmaf(depot[b*2+0], Wd[t], fmaf(depot[b*2+1], Wd[ND + t], bd[t]));
}
__global__ void mean_k(float* __restrict__ out) {
    int b = blockIdx.x, t = threadIdx.x;
    const float* base = out + (size_t)b * HROWS * ND + t;
    float s = 0.0f;
    for (int r = 0; r < HROWS; r++) s += base[(size_t)r * ND];
    out[(size_t)BATCH * HROWS * ND + (size_t)b * ND + t] = s * (1.0f / HROWS);
}

// ---------------- launch ----------------
extern "C" void kernel_launch(void* const* d_in, const int* in_sizes, int n_in,
                              void* d_out, int out_size) {
    const float* loc   = (const float*)d_in[0];
    const float* dl    = (const float*)d_in[1];
    const float* depot = (const float*)d_in[3];
    const float* Wi    = (const float*)d_in[4];
    const float* bi    = (const float*)d_in[5];
    const float* Wd    = (const float*)d_in[6];
    const float* bd    = (const float*)d_in[7];
    const float* Wg1   = (const float*)d_in[8];
    const float* bg1   = (const float*)d_in[9];
    const float* Wg2   = (const float*)d_in[10];
    const float* bg2   = (const float*)d_in[11];
    const float* Wg3   = (const float*)d_in[12];
    const float* bg3   = (const float*)d_in[13];
    const float* gamma = (const float*)d_in[14];
    const float* beta  = (const float*)d_in[15];
    const float* WF    = (const float*)d_in[16];
    const float* bF    = (const float*)d_in[17];
    float* out = (float*)d_out;

    cudaFuncSetAttribute(mma_k<1,true>,  cudaFuncAttributeMaxDynamicSharedMemorySize, SMEM_MMA);
    cudaFuncSetAttribute(mma_k<2,true>,  cudaFuncAttributeMaxDynamicSharedMemorySize, SMEM_MMA);
    cudaFuncSetAttribute(mma_k<3,false>, cudaFuncAttributeMaxDynamicSharedMemorySize, SMEM_MMA);
    cudaFuncSetAttribute(mma_k<4,false>, cudaFuncAttributeMaxDynamicSharedMemorySize, SMEM_MMA);

    init_k <<<1, 64>>>();
    dlmax_k<<<NN/256, 256>>>(dl);
    x_k    <<<(NN+255)/256, 256>>>(loc, dl);
    a_k    <<<dim3(16, 16, BATCH), 256>>>();
    deg_k  <<<NN/8, 256>>>();
    l_k    <<<(int)(((size_t)BATCH*NPTS*NPTS + 255)/256), 256>>>();
    g0_k   <<<(NN*F0D + 255)/256, 256>>>(Wi, bi);
    g0t_k  <<<(NN*F0D + 255)/256, 256>>>(Wi, bi);
    wgt_k  <<<dim3(ND, 3), 256>>>(Wg1, Wg2, Wg3);

    mma_k<1,true> <<<dim3(9, 4, BATCH), 256, SMEM_MMA>>>(nullptr, nullptr, nullptr, nullptr); // LG (+LGt)
    mma_k<2,true> <<<dim3(9, 4, BATCH), 256, SMEM_MMA>>>(nullptr, nullptr, nullptr, nullptr); // LLG
    mma_k<3,false><<<dim3(NN/128, 3),   256, SMEM_MMA>>>(bg1, bg2, bg3, nullptr);             // F1
    bnstat_k<<<F0D, 256>>>();
    bnfin_k <<<1, F0D>>>(gamma, beta, WF, bF);
    mma_k<4,false><<<dim3(NN/128, 1),   256, SMEM_MMA>>>(nullptr, nullptr, nullptr, out);     // final
    dep_k  <<<BATCH, ND>>>(depot, Wd, bd, out);
    mean_k <<<BATCH, ND>>>(out);
}

// round 9
// speedup vs baseline: 3.2917x; 3.2917x over previous
#include <cuda_runtime.h>
#include <math.h>
#include <stdint.h>

#define BATCH 32
#define NPTS  512
#define NN    (BATCH*NPTS)     // 16384
#define ND    128
#define F0D   384
#define CATD  1152
#define HROWS 513

// ---------------- scratch (device globals) ----------------
__device__ float g_L  [(size_t)BATCH*NPTS*NPTS];   // A then L in place
__device__ float g_U  [(size_t)NN*64];             // [M | LM | LLM | 0pad] per point
__device__ float g_Mt [(size_t)BATCH*20*NPTS];     // per batch [mono][point]
__device__ float g_LMt[(size_t)BATCH*20*NPTS];     // per batch [mono][point] of L@M
__device__ float g_P  [(size_t)3*20*F0D];          // P0 | Psq | Pcu  [20 x 384] each
__device__ float g_R  [(size_t)64*F0D];            // [64 x 384], rows 60..63 zero
__device__ float g_F0 [(size_t)NN*F0D];
__device__ float g_F1 [(size_t)NN*F0D];
__device__ float g_X  [NN*3];
__device__ float g_deg[NN];
__device__ float g_ps [(size_t)128*F0D];
__device__ float g_pq [(size_t)128*F0D];
__device__ float g_bnsum[F0D];
__device__ float g_bnsq [F0D];
__device__ float g_scale[F0D];
__device__ float g_colbias[ND];
__device__ unsigned g_dlmax_bits;
__device__ unsigned g_amax_bits;

// ---------------- small kernels (proven) ----------------
__global__ void init_k() {
    if (threadIdx.x == 0) { g_dlmax_bits = 0u; g_amax_bits = 0u; }
}
__global__ void dlmax_k(const float* __restrict__ dl) {
    int i = blockIdx.x * blockDim.x + threadIdx.x;
    float v = dl[i];
    #pragma unroll
    for (int o = 16; o; o >>= 1) v = fmaxf(v, __shfl_xor_sync(0xffffffff, v, o));
    if ((threadIdx.x & 31) == 0) atomicMax(&g_dlmax_bits, __float_as_uint(v));
}
__global__ void x_k(const float* __restrict__ loc, const float* __restrict__ dl) {
    int i = blockIdx.x * blockDim.x + threadIdx.x;
    if (i >= NN) return;
    float inv = 1.0f / __uint_as_float(g_dlmax_bits);
    g_X[i*3+0] = loc[i*2+0];
    g_X[i*3+1] = loc[i*2+1];
    g_X[i*3+2] = dl[i] * inv;
}
__global__ void a_k() {
    int b  = blockIdx.z;
    int i0 = blockIdx.y * 32, j0 = blockIdx.x * 32;
    __shared__ float Xi[32][3], Xj[32][3];
    int t = threadIdx.x;
    if (t < 96)       ((float*)Xi)[t]    = g_X[((size_t)b*NPTS + i0)*3 + t];
    else if (t < 192) ((float*)Xj)[t-96] = g_X[((size_t)b*NPTS + j0)*3 + (t-96)];
    __syncthreads();
    int tx = t & 31, ty = t >> 5;
    float xj0 = Xj[tx][0], xj1 = Xj[tx][1], xj2 = Xj[tx][2];
    float m = 0.0f;
    float* Ab = g_L + (size_t)b * NPTS * NPTS;
    #pragma unroll
    for (int r = 0; r < 4; r++) {
        int i = ty * 4 + r;
        float dx = Xi[i][0]-xj0, dy = Xi[i][1]-xj1, dz = Xi[i][2]-xj2;
        float d2 = dx*dx + dy*dy + dz*dz;
        float v  = (i0 + i == j0 + tx) ? 0.0f : rsqrtf(d2);
        Ab[(size_t)(i0+i)*NPTS + j0 + tx] = v;
        m = fmaxf(m, v);
    }
    #pragma unroll
    for (int o = 16; o; o >>= 1) m = fmaxf(m, __shfl_xor_sync(0xffffffff, m, o));
    __shared__ float wm[8];
    if (tx == 0) wm[ty] = m;
    __syncthreads();
    if (t == 0) {
        float mm = wm[0];
        #pragma unroll
        for (int w = 1; w < 8; w++) mm = fmaxf(mm, wm[w]);
        atomicMax(&g_amax_bits, __float_as_uint(mm));
    }
}
__global__ void deg_k() {
    int gw   = (blockIdx.x * blockDim.x + threadIdx.x) >> 5;
    int lane = threadIdx.x & 31;
    if (gw >= NN) return;
    const float4* row = (const float4*)(g_L + (size_t)gw * NPTS);
    float s = 0.0f;
    #pragma unroll
    for (int w = 0; w < 4; w++) { float4 v = row[lane + w*32]; s += v.x+v.y+v.z+v.w; }
    #pragma unroll
    for (int o = 16; o; o >>= 1) s += __shfl_xor_sync(0xffffffff, s, o);
    if (lane == 0) g_deg[gw] = s / __uint_as_float(g_amax_bits) - 1.0f;
}
__global__ void l_k() {
    size_t idx = (size_t)blockIdx.x * blockDim.x + threadIdx.x;
    if (idx >= (size_t)BATCH*NPTS*NPTS) return;
    float inv = 1.0f / __uint_as_float(g_amax_bits);
    int    j  = (int)(idx & 511);
    size_t r  = idx >> 9;
    int    i  = (int)(r & 511);
    float v = -g_L[idx] * inv;
    if (i == j) v += g_deg[r];
    g_L[idx] = v;
}

// ---------------- monomials: U[:,0:20] = M, Mt = M^T per batch ----------------
__global__ void mono_k() {
    int i = blockIdx.x * blockDim.x + threadIdx.x;
    if (i >= NN) return;
    float x = g_X[i*3], y = g_X[i*3+1], z = g_X[i*3+2];
    float m[20];
    m[0]=1.0f; m[1]=x; m[2]=y; m[3]=z;
    m[4]=x*x; m[5]=x*y; m[6]=x*z; m[7]=y*y; m[8]=y*z; m[9]=z*z;
    m[10]=m[4]*x; m[11]=m[4]*y; m[12]=m[4]*z; m[13]=x*m[7]; m[14]=m[5]*z;
    m[15]=x*m[9]; m[16]=m[7]*y; m[17]=m[7]*z; m[18]=y*m[9]; m[19]=m[9]*z;
    float* u = g_U + (size_t)i*64;
    #pragma unroll
    for (int p = 0; p < 20; p++) u[p] = m[p];
    u[60]=0.f; u[61]=0.f; u[62]=0.f; u[63]=0.f;
    int b = i >> 9, nl = i & 511;
    #pragma unroll
    for (int p = 0; p < 20; p++) g_Mt[(size_t)b*20*NPTS + p*NPTS + nl] = m[p];
}

// ---------------- polynomial coefficients of F0, F0^2, F0^3 ----------------
// monomial order: 1,x,y,z, x2,xy,xz,y2,yz,z2, x3,x2y,x2z,xy2,xyz,xz2,y3,y2z,yz2,z3
__global__ void pcoef_k(const float* __restrict__ Wi, const float* __restrict__ bi) {
    int j = blockIdx.x * blockDim.x + threadIdx.x;
    if (j >= F0D) return;
    float a = Wi[j], b = Wi[F0D+j], c = Wi[2*F0D+j], d = bi[j];
    float* P0 = g_P;
    float* Ps = g_P + 20*F0D;
    float* Pc = g_P + 40*F0D;
    #pragma unroll
    for (int p = 0; p < 20; p++) { P0[p*F0D+j]=0.f; Ps[p*F0D+j]=0.f; Pc[p*F0D+j]=0.f; }
    // F0 (linear)
    P0[0*F0D+j]=d; P0[1*F0D+j]=a; P0[2*F0D+j]=b; P0[3*F0D+j]=c;
    // F0^2
    Ps[0*F0D+j]=d*d;     Ps[1*F0D+j]=2.f*a*d; Ps[2*F0D+j]=2.f*b*d; Ps[3*F0D+j]=2.f*c*d;
    Ps[4*F0D+j]=a*a;     Ps[5*F0D+j]=2.f*a*b; Ps[6*F0D+j]=2.f*a*c; Ps[7*F0D+j]=b*b;
    Ps[8*F0D+j]=2.f*b*c; Ps[9*F0D+j]=c*c;
    // F0^3
    Pc[0*F0D+j]=d*d*d;
    Pc[1*F0D+j]=3.f*a*d*d;  Pc[2*F0D+j]=3.f*b*d*d;  Pc[3*F0D+j]=3.f*c*d*d;
    Pc[4*F0D+j]=3.f*a*a*d;  Pc[5*F0D+j]=6.f*a*b*d;  Pc[6*F0D+j]=6.f*a*c*d;
    Pc[7*F0D+j]=3.f*b*b*d;  Pc[8*F0D+j]=6.f*b*c*d;  Pc[9*F0D+j]=3.f*c*c*d;
    Pc[10*F0D+j]=a*a*a;     Pc[11*F0D+j]=3.f*a*a*b; Pc[12*F0D+j]=3.f*a*a*c;
    Pc[13*F0D+j]=3.f*a*b*b; Pc[14*F0D+j]=6.f*a*b*c; Pc[15*F0D+j]=3.f*a*c*c;
    Pc[16*F0D+j]=b*b*b;     Pc[17*F0D+j]=3.f*b*b*c; Pc[18*F0D+j]=3.f*b*c*c;
    Pc[19*F0D+j]=c*c*c;
}

// ---------------- R[64 x 384]: R[t*20+p][kb*128+jj] = sum_j Ppoly(kb)[p][j]*Wg_kb[(t*384+j)*128+jj]
__global__ void rbuild_k(const float* __restrict__ W1, const float* __restrict__ W2,
                         const float* __restrict__ W3) {
    int p  = blockIdx.x;           // 0..63
    int kb = blockIdx.y;           // 0..2
    int jj = threadIdx.x;          // 0..127
    if (p >= 60) { g_R[(size_t)p*F0D + kb*ND + jj] = 0.f; return; }
    const float* Wg = (kb == 0) ? W1 : (kb == 1 ? W2 : W3);
    const float* P  = g_P + (size_t)kb*20*F0D + (size_t)(p % 20)*F0D;
    int t = p / 20;
    float s = 0.f;
    for (int j = 0; j < F0D; j++)
        s = fmaf(P[j], Wg[(size_t)(t*F0D + j)*ND + jj], s);
    g_R[(size_t)p*F0D + kb*ND + jj] = s;
}

// ---------------- L propagation: out_row = L_row @ M (20 cols) ----------------
// mode 0: Mt -> U[:,20:40] + LMt ; mode 1: LMt -> U[:,40:60]
__global__ void __launch_bounds__(256) lprop_k(int mode) {
    __shared__ float Ms[20*NPTS];          // 40 KB
    int b = blockIdx.y;
    const float* src = (mode ? g_LMt : g_Mt) + (size_t)b*20*NPTS;
    for (int i = threadIdx.x; i < 20*NPTS; i += 256) Ms[i] = src[i];
    __syncthreads();
    int wid = threadIdx.x >> 5, lane = threadIdx.x & 31;
    #pragma unroll 1
    for (int rr = 0; rr < 8; rr++) {
        int il = blockIdx.x*64 + wid*8 + rr;
        const float* Lr = g_L + ((size_t)b*NPTS + il)*NPTS;
        float acc[20];
        #pragma unroll
        for (int c = 0; c < 20; c++) acc[c] = 0.f;
        #pragma unroll 4
        for (int t = 0; t < 16; t++) {
            float lv = Lr[lane + 32*t];
            #pragma unroll
            for (int c = 0; c < 20; c++)
                acc[c] = fmaf(lv, Ms[c*NPTS + lane + 32*t], acc[c]);
        }
        #pragma unroll
        for (int c = 0; c < 20; c++) {
            float v = acc[c];
            #pragma unroll
            for (int o = 16; o; o >>= 1) v += __shfl_xor_sync(0xffffffff, v, o);
            acc[c] = v;
        }
        if (lane == 0) {
            float* u = g_U + ((size_t)b*NPTS + il)*64 + (mode ? 40 : 20);
            #pragma unroll
            for (int c = 0; c < 20; c++) u[c] = acc[c];
            if (!mode) {
                #pragma unroll
                for (int c = 0; c < 20; c++)
                    g_LMt[(size_t)b*20*NPTS + c*NPTS + il] = acc[c];
            }
        }
    }
}

// ---------------- F0 (residual source), pointwise ----------------
__global__ void f0_k(const float* __restrict__ Wi, const float* __restrict__ bi) {
    int t = blockIdx.x * blockDim.x + threadIdx.x;
    if (t >= NN * F0D) return;
    int row = t / F0D, j = t - row * F0D;
    const float* x = &g_X[row*3];
    g_F0[t] = fmaf(x[0], Wi[j], fmaf(x[1], Wi[F0D+j], fmaf(x[2], Wi[2*F0D+j], bi[j])));
}

// ---------------- F1 = leaky(U @ R + bg) + F0 ;  [16384x64]@[64x384] ----------------
__global__ void __launch_bounds__(256) f1gemm_k(
    const float* __restrict__ bg1, const float* __restrict__ bg2, const float* __restrict__ bg3)
{
    int bm = blockIdx.x * 128;
    int kb = blockIdx.y;                       // col block 0..2
    const float* bg = (kb == 0) ? bg1 : (kb == 1 ? bg2 : bg3);
    __shared__ float As[8][128], Bs[8][128];
    int t = threadIdx.x;
    int arow = t >> 1, acol = (t & 1) * 4;
    int brow = t >> 5, bcol = (t & 31) * 4;
    int tx = t & 15, ty = t >> 4;
    float acc[8][8] = {};
    const float* Aptr = g_U + (size_t)(bm + arow) * 64 + acol;
    const float* Bptr = g_R + (size_t)brow * F0D + kb * ND + bcol;
    for (int k0 = 0; k0 < 64; k0 += 8) {
        float4 av = *(const float4*)(Aptr + k0);
        float4 bv = *(const float4*)(Bptr + (size_t)k0 * F0D);
        As[acol+0][arow] = av.x; As[acol+1][arow] = av.y;
        As[acol+2][arow] = av.z; As[acol+3][arow] = av.w;
        *(float4*)&Bs[brow][bcol] = bv;
        __syncthreads();
        #pragma unroll
        for (int kk = 0; kk < 8; kk++) {
            float ra[8], rb[8];
            *(float4*)(ra)   = *(float4*)&As[kk][ty*4];
            *(float4*)(ra+4) = *(float4*)&As[kk][64 + ty*4];
            *(float4*)(rb)   = *(float4*)&Bs[kk][tx*4];
            *(float4*)(rb+4) = *(float4*)&Bs[kk][64 + tx*4];
            #pragma unroll
            for (int i = 0; i < 8; i++)
                #pragma unroll
                for (int j = 0; j < 8; j++) acc[i][j] = fmaf(ra[i], rb[j], acc[i][j]);
        }
        __syncthreads();
    }
    #pragma unroll
    for (int i = 0; i < 8; i++) {
        int r = bm + ((i < 4) ? ty*4 + i : 64 + ty*4 + (i-4));
        #pragma unroll
        for (int jj = 0; jj < 8; jj++) {
            int c = (jj < 4) ? tx*4 + jj : 64 + tx*4 + (jj-4);
            float v = acc[i][jj] + bg[c];
            v = (v > 0.0f) ? v : 0.01f * v;
            v += g_F0[(size_t)r * F0D + kb * ND + c];
            g_F1[(size_t)r * F0D + kb * ND + c] = v;
        }
    }
}

// ---------------- BN stats (two-pass, deterministic, coalesced) ----------------
__global__ void bnpart_k() {
    int rb = blockIdx.x, t = threadIdx.x;          // 128 blocks x 384 threads
    float s = 0.f, q = 0.f;
    const float* base = g_F1 + (size_t)rb*128*F0D + t;
    #pragma unroll 4
    for (int r = 0; r < 128; r++) { float v = base[(size_t)r*F0D]; s += v; q += v*v; }
    g_ps[(size_t)rb*F0D + t] = s; g_pq[(size_t)rb*F0D + t] = q;
}
__global__ void bnred_k() {
    int t = threadIdx.x;                           // 384 threads
    float s = 0.f, q = 0.f;
    for (int rb = 0; rb < 128; rb++) { s += g_ps[(size_t)rb*F0D + t]; q += g_pq[(size_t)rb*F0D + t]; }
    g_bnsum[t] = s; g_bnsq[t] = q;
}
__global__ void bnfin_k(const float* __restrict__ gamma, const float* __restrict__ beta,
                        const float* __restrict__ WF,    const float* __restrict__ bF) {
    __shared__ float sh[F0D];
    int t = threadIdx.x;                           // 384 threads
    float mu   = g_bnsum[t] * (1.0f / NN);
    float var  = g_bnsq[t]  * (1.0f / NN) - mu * mu;
    float sc   = gamma[t] * rsqrtf(var + 1e-5f);
    g_scale[t] = sc;
    sh[t]      = beta[t] - mu * sc;
    __syncthreads();
    if (t < ND) {
        float s = bF[t];
        for (int k = 0; k < F0D; k++) s = fmaf(sh[k], WF[(size_t)k * ND + t], s);
        g_colbias[t] = s;
    }
}

// ---------------- final GEMM (proven): leaky((F1*scale)@WF + colbias) ----------------
__global__ void __launch_bounds__(256) fgemm_k(const float* __restrict__ WF, float* __restrict__ out) {
    int bm = blockIdx.x * 128;
    __shared__ float As[8][128], Bs[8][128];
    int t = threadIdx.x;
    int arow = t >> 1, acol = (t & 1) * 4;
    int brow = t >> 5, bcol = (t & 31) * 4;
    int tx = t & 15, ty = t >> 4;
    float acc[8][8] = {};
    const float* Aptr = g_F1 + (size_t)(bm + arow) * F0D + acol;
    for (int k0 = 0; k0 < F0D; k0 += 8) {
        float4 av = *(const float4*)(Aptr + k0);
        float4 sc = *(const float4*)&g_scale[k0 + acol];
        av.x *= sc.x; av.y *= sc.y; av.z *= sc.z; av.w *= sc.w;
        float4 bv = *(const float4*)(WF + (size_t)(k0 + brow) * ND + bcol);
        As[acol+0][arow] = av.x; As[acol+1][arow] = av.y;
        As[acol+2][arow] = av.z; As[acol+3][arow] = av.w;
        *(float4*)&Bs[brow][bcol] = bv;
        __syncthreads();
        #pragma unroll
        for (int kk = 0; kk < 8; kk++) {
            float ra[8], rb[8];
            *(float4*)(ra)   = *(float4*)&As[kk][ty*4];
            *(float4*)(ra+4) = *(float4*)&As[kk][64 + ty*4];
            *(float4*)(rb)   = *(float4*)&Bs[kk][tx*4];
            *(float4*)(rb+4) = *(float4*)&Bs[kk][64 + tx*4];
            #pragma unroll
            for (int i = 0; i < 8; i++)
                #pragma unroll
                for (int j = 0; j < 8; j++) acc[i][j] = fmaf(ra[i], rb[j], acc[i][j]);
        }
        __syncthreads();
    }
    #pragma unroll
    for (int i = 0; i < 8; i++) {
        int r    = bm + ((i < 4) ? ty*4 + i : 64 + ty*4 + (i-4));
        int b    = r >> 9;
        int nloc = r & 511;
        float* orow = out + ((size_t)b * HROWS + 1 + nloc) * ND;
        float v4[8];
        #pragma unroll
        for (int jj = 0; jj < 8; jj++) {
            int c = (jj < 4) ? tx*4 + jj : 64 + tx*4 + (jj-4);
            float v = acc[i][jj] + g_colbias[c];
            v4[jj] = (v > 0.0f) ? v : 0.01f * v;
        }
        *(float4*)(orow + tx*4)      = *(float4*)&v4[0];
        *(float4*)(orow + 64 + tx*4) = *(float4*)&v4[4];
    }
}
__global__ void dep_k(const float* __restrict__ depot, const float* __restrict__ Wd,
                      const float* __restrict__ bd, float* __restrict__ out) {
    int b = blockIdx.x, t = threadIdx.x;
    out[(size_t)b * HROWS * ND + t] =
        fmaf(depot[b*2+0], Wd[t], fmaf(depot[b*2+1], Wd[ND + t], bd[t]));
}
__global__ void mean_k(float* __restrict__ out) {
    int b = blockIdx.x, t = threadIdx.x;
    const float* base = out + (size_t)b * HROWS * ND + t;
    float s = 0.0f;
    for (int r = 0; r < HROWS; r++) s += base[(size_t)r * ND];
    out[(size_t)BATCH * HROWS * ND + (size_t)b * ND + t] = s * (1.0f / HROWS);
}

// ---------------- launch ----------------
extern "C" void kernel_launch(void* const* d_in, const int* in_sizes, int n_in,
                              void* d_out, int out_size) {
    const float* loc   = (const float*)d_in[0];
    const float* dl    = (const float*)d_in[1];
    const float* depot = (const float*)d_in[3];
    const float* Wi    = (const float*)d_in[4];
    const float* bi    = (const float*)d_in[5];
    const float* Wd    = (const float*)d_in[6];
    const float* bd    = (const float*)d_in[7];
    const float* Wg1   = (const float*)d_in[8];
    const float* bg1   = (const float*)d_in[9];
    const float* Wg2   = (const float*)d_in[10];
    const float* bg2   = (const float*)d_in[11];
    const float* Wg3   = (const float*)d_in[12];
    const float* bg3   = (const float*)d_in[13];
    const float* gamma = (const float*)d_in[14];
    const float* beta  = (const float*)d_in[15];
    const float* WF    = (const float*)d_in[16];
    const float* bF    = (const float*)d_in[17];
    float* out = (float*)d_out;

    init_k  <<<1, 64>>>();
    dlmax_k <<<NN/256, 256>>>(dl);
    x_k     <<<(NN+255)/256, 256>>>(loc, dl);
    a_k     <<<dim3(16, 16, BATCH), 256>>>();
    deg_k   <<<NN/8, 256>>>();
    l_k     <<<(int)(((size_t)BATCH*NPTS*NPTS + 255)/256), 256>>>();
    mono_k  <<<(NN+255)/256, 256>>>();
    pcoef_k <<<(F0D+127)/128, 128>>>(Wi, bi);
    rbuild_k<<<dim3(64, 3), ND>>>(Wg1, Wg2, Wg3);
    f0_k    <<<(NN*F0D + 255)/256, 256>>>(Wi, bi);
    lprop_k <<<dim3(8, BATCH), 256>>>(0);          // LM
    lprop_k <<<dim3(8, BATCH), 256>>>(1);          // LLM
    f1gemm_k<<<dim3(NN/128, 3), 256>>>(bg1, bg2, bg3);
    bnpart_k<<<128, F0D>>>();
    bnred_k <<<1, F0D>>>();
    bnfin_k <<<1, F0D>>>(gamma, beta, WF, bF);
    fgemm_k <<<NN/128, 256>>>(WF, out);
    dep_k   <<<BATCH, ND>>>(depot, Wd, bd, out);
    mean_k  <<<BATCH, ND>>>(out);
}

// round 10
// speedup vs baseline: 4.1144x; 1.2499x over previous
#include <cuda_runtime.h>
#include <math.h>
#include <stdint.h>

#define BATCH 32
#define NPTS  512
#define NN    (BATCH*NPTS)     // 16384
#define ND    128
#define F0D   384
#define CATD  1152
#define HROWS 513

// ---------------- scratch (device globals) ----------------
__device__ float g_L  [(size_t)BATCH*NPTS*NPTS];   // raw A (never converted to L)
__device__ float g_U  [(size_t)NN*64];             // [M | LM | LLM | 0pad]
__device__ float g_Mt [(size_t)BATCH*20*NPTS];     // per batch [mono][point]
__device__ float g_LMt[(size_t)BATCH*20*NPTS];     // per batch [mono][point] of L@M
__device__ float g_R  [(size_t)64*F0D];            // rows 60..63 zero
__device__ float g_F1 [(size_t)NN*F0D];
__device__ float g_X  [NN*3];
__device__ float g_deg[NN];
__device__ float g_ps [(size_t)128*F0D];           // BN partial sums per row-block
__device__ float g_pq [(size_t)128*F0D];
__device__ unsigned g_dlmax_bits;
__device__ unsigned g_amax_bits;

// ---------------- small kernels ----------------
__global__ void init_k() {
    if (threadIdx.x == 0) { g_dlmax_bits = 0u; g_amax_bits = 0u; }
}
__global__ void dlmax_k(const float* __restrict__ dl) {
    int i = blockIdx.x * blockDim.x + threadIdx.x;
    float v = dl[i];
    #pragma unroll
    for (int o = 16; o; o >>= 1) v = fmaxf(v, __shfl_xor_sync(0xffffffff, v, o));
    if ((threadIdx.x & 31) == 0) atomicMax(&g_dlmax_bits, __float_as_uint(v));
}
// X + monomials (U[0:20], zero pad 60:63) + Mt
__global__ void mono_k(const float* __restrict__ loc, const float* __restrict__ dl) {
    int i = blockIdx.x * blockDim.x + threadIdx.x;
    if (i >= NN) return;
    float inv = 1.0f / __uint_as_float(g_dlmax_bits);
    float x = loc[i*2+0], y = loc[i*2+1], z = dl[i] * inv;
    g_X[i*3+0] = x; g_X[i*3+1] = y; g_X[i*3+2] = z;
    float m[20];
    m[0]=1.0f; m[1]=x; m[2]=y; m[3]=z;
    m[4]=x*x; m[5]=x*y; m[6]=x*z; m[7]=y*y; m[8]=y*z; m[9]=z*z;
    m[10]=m[4]*x; m[11]=m[4]*y; m[12]=m[4]*z; m[13]=x*m[7]; m[14]=m[5]*z;
    m[15]=x*m[9]; m[16]=m[7]*y; m[17]=m[7]*z; m[18]=y*m[9]; m[19]=m[9]*z;
    float* u = g_U + (size_t)i*64;
    #pragma unroll
    for (int p = 0; p < 20; p++) u[p] = m[p];
    u[60]=0.f; u[61]=0.f; u[62]=0.f; u[63]=0.f;
    int b = i >> 9, nl = i & 511;
    #pragma unroll
    for (int p = 0; p < 20; p++) g_Mt[(size_t)b*20*NPTS + p*NPTS + nl] = m[p];
}
__global__ void a_k() {
    int b  = blockIdx.z;
    int i0 = blockIdx.y * 32, j0 = blockIdx.x * 32;
    __shared__ float Xi[32][3], Xj[32][3];
    int t = threadIdx.x;
    if (t < 96)       ((float*)Xi)[t]    = g_X[((size_t)b*NPTS + i0)*3 + t];
    else if (t < 192) ((float*)Xj)[t-96] = g_X[((size_t)b*NPTS + j0)*3 + (t-96)];
    __syncthreads();
    int tx = t & 31, ty = t >> 5;
    float xj0 = Xj[tx][0], xj1 = Xj[tx][1], xj2 = Xj[tx][2];
    float m = 0.0f;
    float* Ab = g_L + (size_t)b * NPTS * NPTS;
    #pragma unroll
    for (int r = 0; r < 4; r++) {
        int i = ty * 4 + r;
        float dx = Xi[i][0]-xj0, dy = Xi[i][1]-xj1, dz = Xi[i][2]-xj2;
        float d2 = dx*dx + dy*dy + dz*dz;
        float v  = (i0 + i == j0 + tx) ? 0.0f : rsqrtf(d2);
        Ab[(size_t)(i0+i)*NPTS + j0 + tx] = v;
        m = fmaxf(m, v);
    }
    #pragma unroll
    for (int o = 16; o; o >>= 1) m = fmaxf(m, __shfl_xor_sync(0xffffffff, m, o));
    __shared__ float wm[8];
    if (tx == 0) wm[ty] = m;
    __syncthreads();
    if (t == 0) {
        float mm = wm[0];
        #pragma unroll
        for (int w = 1; w < 8; w++) mm = fmaxf(mm, wm[w]);
        atomicMax(&g_amax_bits, __float_as_uint(mm));
    }
}

// ---------------- polynomial coefficient (power kb+1, monomial pm) ----------------
__device__ __forceinline__ float coefP(int kb, int pm, float a, float b, float c, float d) {
    if (kb == 0) {
        switch (pm) { case 0: return d; case 1: return a; case 2: return b; case 3: return c; }
        return 0.f;
    } else if (kb == 1) {
        switch (pm) {
            case 0: return d*d;     case 1: return 2.f*a*d; case 2: return 2.f*b*d;
            case 3: return 2.f*c*d; case 4: return a*a;     case 5: return 2.f*a*b;
            case 6: return 2.f*a*c; case 7: return b*b;     case 8: return 2.f*b*c;
            case 9: return c*c;
        }
        return 0.f;
    }
    switch (pm) {
        case 0:  return d*d*d;     case 1:  return 3.f*a*d*d; case 2:  return 3.f*b*d*d;
        case 3:  return 3.f*c*d*d; case 4:  return 3.f*a*a*d; case 5:  return 6.f*a*b*d;
        case 6:  return 6.f*a*c*d; case 7:  return 3.f*b*b*d; case 8:  return 6.f*b*c*d;
        case 9:  return 3.f*c*c*d; case 10: return a*a*a;     case 11: return 3.f*a*a*b;
        case 12: return 3.f*a*a*c; case 13: return 3.f*a*b*b; case 14: return 6.f*a*b*c;
        case 15: return 3.f*a*c*c; case 16: return b*b*b;     case 17: return 3.f*b*b*c;
        case 18: return 3.f*b*c*c; case 19: return c*c*c;
    }
    return 0.f;
}

// R[p][kb*128+jj] = sum_j coefP(kb, p%20)(Wi col j) * Wg_kb[((p/20)*384 + j)*128 + jj]
__global__ void rbuild_k(const float* __restrict__ W1, const float* __restrict__ W2,
                         const float* __restrict__ W3, const float* __restrict__ Wi,
                         const float* __restrict__ bi) {
    int p  = blockIdx.x;           // 0..63
    int kb = blockIdx.y;           // 0..2
    int jj = threadIdx.x;          // 0..127
    if (p >= 60) { g_R[(size_t)p*F0D + kb*ND + jj] = 0.f; return; }
    __shared__ float sa[F0D], sb[F0D], sc_[F0D], sd[F0D];
    for (int j = jj; j < F0D; j += 128) {
        sa[j] = Wi[j]; sb[j] = Wi[F0D+j]; sc_[j] = Wi[2*F0D+j]; sd[j] = bi[j];
    }
    __syncthreads();
    int t = p / 20, pm = p % 20;
    const float* Wg = (kb == 0) ? W1 : (kb == 1 ? W2 : W3);
    float s = 0.f;
    for (int j = 0; j < F0D; j++) {
        float C = coefP(kb, pm, sa[j], sb[j], sc_[j], sd[j]);
        s = fmaf(C, Wg[(size_t)(t*F0D + j)*ND + jj], s);
    }
    g_R[(size_t)p*F0D + kb*ND + jj] = s;
}

// ---------------- L propagation from RAW A: LM = deg*m - inv*(A@M) ----------------
// mode 0: Mt -> U[20:40] + LMt + deg ; mode 1: LMt -> U[40:60]
__global__ void __launch_bounds__(256) lprop_k(int mode) {
    __shared__ float Ms[20*NPTS];          // 40 KB
    int b = blockIdx.y;
    const float* src = (mode ? g_LMt : g_Mt) + (size_t)b*20*NPTS;
    for (int i = threadIdx.x; i < 20*NPTS; i += 256) Ms[i] = src[i];
    __syncthreads();
    float inv = 1.0f / __uint_as_float(g_amax_bits);
    int wid = threadIdx.x >> 5, lane = threadIdx.x & 31;
    #pragma unroll 1
    for (int rr = 0; rr < 8; rr++) {
        int il = blockIdx.x*64 + wid*8 + rr;
        const float* Ar = g_L + ((size_t)b*NPTS + il)*NPTS;
        float acc[20]; float rs = 0.f;
        #pragma unroll
        for (int c = 0; c < 20; c++) acc[c] = 0.f;
        #pragma unroll 4
        for (int t = 0; t < 16; t++) {
            float av = Ar[lane + 32*t];
            rs += av;
            #pragma unroll
            for (int c = 0; c < 20; c++)
                acc[c] = fmaf(av, Ms[c*NPTS + lane + 32*t], acc[c]);
        }
        #pragma unroll
        for (int o = 16; o; o >>= 1) rs += __shfl_xor_sync(0xffffffff, rs, o);
        #pragma unroll
        for (int c = 0; c < 20; c++) {
            float v = acc[c];
            #pragma unroll
            for (int o = 16; o; o >>= 1) v += __shfl_xor_sync(0xffffffff, v, o);
            acc[c] = v;
        }
        if (lane == 0) {
            float deg;
            if (!mode) { deg = rs * inv - 1.0f; g_deg[(size_t)b*NPTS + il] = deg; }
            else        deg = g_deg[(size_t)b*NPTS + il];
            float* u = g_U + ((size_t)b*NPTS + il)*64 + (mode ? 40 : 20);
            #pragma unroll
            for (int c = 0; c < 20; c++) {
                float o = deg * Ms[c*NPTS + il] - acc[c] * inv;
                u[c] = o;
                if (!mode) g_LMt[(size_t)b*20*NPTS + c*NPTS + il] = o;
            }
        }
    }
}

// ---------------- F1 = leaky(U@R + bg) + F0(inline) ; epilogue: BN partials ----------------
__global__ void __launch_bounds__(256) f1gemm_k(
    const float* __restrict__ bg1, const float* __restrict__ bg2, const float* __restrict__ bg3,
    const float* __restrict__ Wi,  const float* __restrict__ bi)
{
    int bm = blockIdx.x * 128;
    int kb = blockIdx.y;
    const float* bg = (kb == 0) ? bg1 : (kb == 1 ? bg2 : bg3);
    __shared__ float As[8][128], Bs[8][128];
    __shared__ float sWa[128], sWb[128], sWc[128], sbi[128], sx[128], sy[128], sz[128];
    __shared__ float redS[16][128], redQ[16][128];
    int t = threadIdx.x;
    if (t < 128) {
        int c = kb*128 + t;
        sWa[t] = Wi[c]; sWb[t] = Wi[F0D+c]; sWc[t] = Wi[2*F0D+c]; sbi[t] = bi[c];
        int r = bm + t;
        sx[t] = g_X[(size_t)r*3]; sy[t] = g_X[(size_t)r*3+1]; sz[t] = g_X[(size_t)r*3+2];
    }
    int arow = t >> 1, acol = (t & 1) * 4;
    int brow = t >> 5, bcol = (t & 31) * 4;
    int tx = t & 15, ty = t >> 4;
    float acc[8][8] = {};
    const float* Aptr = g_U + (size_t)(bm + arow) * 64 + acol;
    const float* Bptr = g_R + (size_t)brow * F0D + kb * ND + bcol;
    __syncthreads();
    for (int k0 = 0; k0 < 64; k0 += 8) {
        float4 av = *(const float4*)(Aptr + k0);
        float4 bv = *(const float4*)(Bptr + (size_t)k0 * F0D);
        As[acol+0][arow] = av.x; As[acol+1][arow] = av.y;
        As[acol+2][arow] = av.z; As[acol+3][arow] = av.w;
        *(float4*)&Bs[brow][bcol] = bv;
        __syncthreads();
        #pragma unroll
        for (int kk = 0; kk < 8; kk++) {
            float ra[8], rb[8];
            *(float4*)(ra)   = *(float4*)&As[kk][ty*4];
            *(float4*)(ra+4) = *(float4*)&As[kk][64 + ty*4];
            *(float4*)(rb)   = *(float4*)&Bs[kk][tx*4];
            *(float4*)(rb+4) = *(float4*)&Bs[kk][64 + tx*4];
            #pragma unroll
            for (int i = 0; i < 8; i++)
                #pragma unroll
                for (int j = 0; j < 8; j++) acc[i][j] = fmaf(ra[i], rb[j], acc[i][j]);
        }
        __syncthreads();
    }
    float cS[8] = {}, cQ[8] = {};
    #pragma unroll
    for (int i = 0; i < 8; i++) {
        int rloc = (i < 4) ? ty*4 + i : 64 + ty*4 + (i-4);
        int r = bm + rloc;
        #pragma unroll
        for (int jj = 0; jj < 8; jj++) {
            int cloc = (jj < 4) ? tx*4 + jj : 64 + tx*4 + (jj-4);
            float v = acc[i][jj] + bg[cloc];
            v = (v > 0.0f) ? v : 0.01f * v;
            v += fmaf(sx[rloc], sWa[cloc],
                 fmaf(sy[rloc], sWb[cloc],
                 fmaf(sz[rloc], sWc[cloc], sbi[cloc])));
            g_F1[(size_t)r * F0D + kb * ND + cloc] = v;
            cS[jj] += v; cQ[jj] += v * v;
        }
    }
    #pragma unroll
    for (int jj = 0; jj < 8; jj++) {
        int cloc = (jj < 4) ? tx*4 + jj : 64 + tx*4 + (jj-4);
        redS[ty][cloc] = cS[jj]; redQ[ty][cloc] = cQ[jj];
    }
    __syncthreads();
    if (t < 128) {
        float s = 0.f, q = 0.f;
        #pragma unroll
        for (int g = 0; g < 16; g++) { s += redS[g][t]; q += redQ[g][t]; }
        g_ps[(size_t)blockIdx.x * F0D + kb * ND + t] = s;
        g_pq[(size_t)blockIdx.x * F0D + kb * ND + t] = q;
    }
}

// ---------------- final GEMM with fused BN finalize in prologue ----------------
__global__ void __launch_bounds__(256) fgemm_k(
    const float* __restrict__ WF, const float* __restrict__ bF,
    const float* __restrict__ gamma, const float* __restrict__ beta,
    float* __restrict__ out)
{
    __shared__ float As[8][128], Bs[8][128];
    __shared__ float sSC[F0D], sSh[F0D], sCB[ND];
    int t = threadIdx.x;
    // BN finalize: reduce partials, build scale/shift, fold shift into colbias
    for (int c = t; c < F0D; c += 256) {
        float s = 0.f, q = 0.f;
        #pragma unroll 4
        for (int rb = 0; rb < 128; rb++) {
            s += g_ps[(size_t)rb*F0D + c];
            q += g_pq[(size_t)rb*F0D + c];
        }
        float mu  = s * (1.0f / NN);
        float var = q * (1.0f / NN) - mu * mu;
        float sc  = gamma[c] * rsqrtf(var + 1e-5f);
        sSC[c] = sc; sSh[c] = beta[c] - mu * sc;
    }
    __syncthreads();
    if (t < ND) {
        float s = bF[t];
        #pragma unroll 4
        for (int k = 0; k < F0D; k++) s = fmaf(sSh[k], WF[(size_t)k*ND + t], s);
        sCB[t] = s;
    }
    __syncthreads();

    int bm = blockIdx.x * 128;
    int arow = t >> 1, acol = (t & 1) * 4;
    int brow = t >> 5, bcol = (t & 31) * 4;
    int tx = t & 15, ty = t >> 4;
    float acc[8][8] = {};
    const float* Aptr = g_F1 + (size_t)(bm + arow) * F0D + acol;
    for (int k0 = 0; k0 < F0D; k0 += 8) {
        float4 av = *(const float4*)(Aptr + k0);
        float4 sc = *(const float4*)&sSC[k0 + acol];
        av.x *= sc.x; av.y *= sc.y; av.z *= sc.z; av.w *= sc.w;
        float4 bv = *(const float4*)(WF + (size_t)(k0 + brow) * ND + bcol);
        As[acol+0][arow] = av.x; As[acol+1][arow] = av.y;
        As[acol+2][arow] = av.z; As[acol+3][arow] = av.w;
        *(float4*)&Bs[brow][bcol] = bv;
        __syncthreads();
        #pragma unroll
        for (int kk = 0; kk < 8; kk++) {
            float ra[8], rb[8];
            *(float4*)(ra)   = *(float4*)&As[kk][ty*4];
            *(float4*)(ra+4) = *(float4*)&As[kk][64 + ty*4];
            *(float4*)(rb)   = *(float4*)&Bs[kk][tx*4];
            *(float4*)(rb+4) = *(float4*)&Bs[kk][64 + tx*4];
            #pragma unroll
            for (int i = 0; i < 8; i++)
                #pragma unroll
                for (int j = 0; j < 8; j++) acc[i][j] = fmaf(ra[i], rb[j], acc[i][j]);
        }
        __syncthreads();
    }
    #pragma unroll
    for (int i = 0; i < 8; i++) {
        int r    = bm + ((i < 4) ? ty*4 + i : 64 + ty*4 + (i-4));
        int b    = r >> 9;
        int nloc = r & 511;
        float* orow = out + ((size_t)b * HROWS + 1 + nloc) * ND;
        float v4[8];
        #pragma unroll
        for (int jj = 0; jj < 8; jj++) {
            int c = (jj < 4) ? tx*4 + jj : 64 + tx*4 + (jj-4);
            float v = acc[i][jj] + sCB[c];
            v4[jj] = (v > 0.0f) ? v : 0.01f * v;
        }
        *(float4*)(orow + tx*4)      = *(float4*)&v4[0];
        *(float4*)(orow + 64 + tx*4) = *(float4*)&v4[4];
    }
}

// ---------------- depot row + per-batch mean, fused ----------------
__global__ void depmean_k(const float* __restrict__ depot, const float* __restrict__ Wd,
                          const float* __restrict__ bd, float* __restrict__ out) {
    int b = blockIdx.x, t = threadIdx.x;                   // 32 x 512
    __shared__ float sm[4][128];
    __shared__ float depv[128];
    if (t < 128) {
        float v = fmaf(depot[b*2+0], Wd[t], fmaf(depot[b*2+1], Wd[ND + t], bd[t]));
        out[(size_t)b * HROWS * ND + t] = v;
        depv[t] = v;
    }
    __syncthreads();
    int seg = t >> 7, ch = t & 127;
    const float* base = out + (size_t)b * HROWS * ND + ch;
    float s = 0.f;
    int r0 = seg*128 + 1, r1 = r0 + 128;                   // rows 1..512 in 4 segments
    for (int r = r0; r < r1; r++) s += base[(size_t)r * ND];
    sm[seg][ch] = s;
    __syncthreads();
    if (t < 128) {
        float tot = depv[t] + sm[0][t] + sm[1][t] + sm[2][t] + sm[3][t];
        out[(size_t)BATCH * HROWS * ND + (size_t)b * ND + t] = tot * (1.0f / HROWS);
    }
}

// ---------------- launch ----------------
extern "C" void kernel_launch(void* const* d_in, const int* in_sizes, int n_in,
                              void* d_out, int out_size) {
    const float* loc   = (const float*)d_in[0];
    const float* dl    = (const float*)d_in[1];
    const float* depot = (const float*)d_in[3];
    const float* Wi    = (const float*)d_in[4];
    const float* bi    = (const float*)d_in[5];
    const float* Wd    = (const float*)d_in[6];
    const float* bd    = (const float*)d_in[7];
    const float* Wg1   = (const float*)d_in[8];
    const float* bg1   = (const float*)d_in[9];
    const float* Wg2   = (const float*)d_in[10];
    const float* bg2   = (const float*)d_in[11];
    const float* Wg3   = (const float*)d_in[12];
    const float* bg3   = (const float*)d_in[13];
    const float* gamma = (const float*)d_in[14];
    const float* beta  = (const float*)d_in[15];
    const float* WF    = (const float*)d_in[16];
    const float* bF    = (const float*)d_in[17];
    float* out = (float*)d_out;

    init_k   <<<1, 64>>>();
    dlmax_k  <<<NN/256, 256>>>(dl);
    mono_k   <<<(NN+255)/256, 256>>>(loc, dl);
    a_k      <<<dim3(16, 16, BATCH), 256>>>();
    rbuild_k <<<dim3(64, 3), ND>>>(Wg1, Wg2, Wg3, Wi, bi);
    lprop_k  <<<dim3(8, BATCH), 256>>>(0);         // LM  (+ deg)
    lprop_k  <<<dim3(8, BATCH), 256>>>(1);         // LLM
    f1gemm_k <<<dim3(NN/128, 3), 256>>>(bg1, bg2, bg3, Wi, bi);
    fgemm_k  <<<NN/128, 256>>>(WF, bF, gamma, beta, out);
    depmean_k<<<BATCH, 512>>>(depot, Wd, bd, out);
}

// round 12
// speedup vs baseline: 4.9300x; 1.1982x over previous
#include <cuda_runtime.h>
#include <math.h>
#include <stdint.h>

#define BATCH 32
#define NPTS  512
#define NN    (BATCH*NPTS)     // 16384
#define ND    128
#define F0D   384
#define CATD  1152
#define HROWS 513

// ---------------- scratch (device globals) ----------------
__device__ float g_L  [(size_t)BATCH*NPTS*NPTS];   // raw A (never converted to L)
__device__ float g_U  [(size_t)NN*64];             // [M | LM | LLM | 0pad]
__device__ float g_Mt [(size_t)BATCH*20*NPTS];     // per batch [mono][point]
__device__ float g_LMt[(size_t)BATCH*20*NPTS];     // per batch [mono][point] of L@M
__device__ float g_R  [(size_t)64*F0D];            // rows 60..63 zero
__device__ float g_F1 [(size_t)NN*F0D];
__device__ float g_X  [NN*3];
__device__ float g_deg[NN];
__device__ float g_ps [(size_t)128*F0D];           // BN partial sums per row-block
__device__ float g_pq [(size_t)128*F0D];
__device__ unsigned g_dlmax_bits;
__device__ unsigned g_amax_bits;

// ---------------- small kernels ----------------
__global__ void init_k() {
    if (threadIdx.x == 0) { g_dlmax_bits = 0u; g_amax_bits = 0u; }
}
__global__ void dlmax_k(const float* __restrict__ dl) {
    int i = blockIdx.x * blockDim.x + threadIdx.x;
    float v = dl[i];
    #pragma unroll
    for (int o = 16; o; o >>= 1) v = fmaxf(v, __shfl_xor_sync(0xffffffff, v, o));
    if ((threadIdx.x & 31) == 0) atomicMax(&g_dlmax_bits, __float_as_uint(v));
}
// X + monomials (U[0:20], zero pad 60:63) + Mt
__global__ void mono_k(const float* __restrict__ loc, const float* __restrict__ dl) {
    int i = blockIdx.x * blockDim.x + threadIdx.x;
    if (i >= NN) return;
    float inv = 1.0f / __uint_as_float(g_dlmax_bits);
    float x = loc[i*2+0], y = loc[i*2+1], z = dl[i] * inv;
    g_X[i*3+0] = x; g_X[i*3+1] = y; g_X[i*3+2] = z;
    float m[20];
    m[0]=1.0f; m[1]=x; m[2]=y; m[3]=z;
    m[4]=x*x; m[5]=x*y; m[6]=x*z; m[7]=y*y; m[8]=y*z; m[9]=z*z;
    m[10]=m[4]*x; m[11]=m[4]*y; m[12]=m[4]*z; m[13]=x*m[7]; m[14]=m[5]*z;
    m[15]=x*m[9]; m[16]=m[7]*y; m[17]=m[7]*z; m[18]=y*m[9]; m[19]=m[9]*z;
    float* u = g_U + (size_t)i*64;
    #pragma unroll
    for (int p = 0; p < 20; p++) u[p] = m[p];
    u[60]=0.f; u[61]=0.f; u[62]=0.f; u[63]=0.f;
    int b = i >> 9, nl = i & 511;
    #pragma unroll
    for (int p = 0; p < 20; p++) g_Mt[(size_t)b*20*NPTS + p*NPTS + nl] = m[p];
}

// ---------------- A (symmetric): upper-triangle tiles, TRANSPOSED mirror via smem ----------------
__global__ void a_k() {
    int ti = blockIdx.y, tj = blockIdx.x;
    if (ti > tj) return;                       // symmetric: upper tiles only
    int b  = blockIdx.z;
    int i0 = ti * 32, j0 = tj * 32;
    __shared__ float Xi[32][3], Xj[32][3];
    __shared__ float T[32][33];                // padded for transposed read
    int t = threadIdx.x;                       // 256
    if (t < 96)       ((float*)Xi)[t]    = g_X[((size_t)b*NPTS + i0)*3 + t];
    else if (t < 192) ((float*)Xj)[t-96] = g_X[((size_t)b*NPTS + j0)*3 + (t-96)];
    __syncthreads();
    int tx = t & 31, ty = t >> 5;
    float xj0 = Xj[tx][0], xj1 = Xj[tx][1], xj2 = Xj[tx][2];
    float m = 0.0f;
    float* Ab = g_L + (size_t)b * NPTS * NPTS;
    #pragma unroll
    for (int r = 0; r < 4; r++) {
        int i = ty * 4 + r;
        float dx = Xi[i][0]-xj0, dy = Xi[i][1]-xj1, dz = Xi[i][2]-xj2;
        float d2 = dx*dx + dy*dy + dz*dz;
        float v  = (i0 + i == j0 + tx) ? 0.0f : rsqrtf(d2);
        Ab[(size_t)(i0+i)*NPTS + j0 + tx] = v;
        T[i][tx] = v;
        m = fmaxf(m, v);
    }
    #pragma unroll
    for (int o = 16; o; o >>= 1) m = fmaxf(m, __shfl_xor_sync(0xffffffff, m, o));
    __shared__ float wm[8];
    if (tx == 0) wm[ty] = m;
    __syncthreads();
    if (ti < tj) {
        // A[j0+ip][i0+tx] = A[i0+tx][j0+ip] = T[tx][ip]  (transposed read)
        #pragma unroll
        for (int r = 0; r < 4; r++) {
            int ip = ty * 4 + r;
            Ab[(size_t)(j0+ip)*NPTS + i0 + tx] = T[tx][ip];
        }
    }
    if (t == 0) {
        float mm = wm[0];
        #pragma unroll
        for (int w = 1; w < 8; w++) mm = fmaxf(mm, wm[w]);
        atomicMax(&g_amax_bits, __float_as_uint(mm));
    }
}

// ---------------- polynomial coefficient (power kb+1, monomial pm) ----------------
__device__ __forceinline__ float coefP(int kb, int pm, float a, float b, float c, float d) {
    if (kb == 0) {
        switch (pm) { case 0: return d; case 1: return a; case 2: return b; case 3: return c; }
        return 0.f;
    } else if (kb == 1) {
        switch (pm) {
            case 0: return d*d;     case 1: return 2.f*a*d; case 2: return 2.f*b*d;
            case 3: return 2.f*c*d; case 4: return a*a;     case 5: return 2.f*a*b;
            case 6: return 2.f*a*c; case 7: return b*b;     case 8: return 2.f*b*c;
            case 9: return c*c;
        }
        return 0.f;
    }
    switch (pm) {
        case 0:  return d*d*d;     case 1:  return 3.f*a*d*d; case 2:  return 3.f*b*d*d;
        case 3:  return 3.f*c*d*d; case 4:  return 3.f*a*a*d; case 5:  return 6.f*a*b*d;
        case 6:  return 6.f*a*c*d; case 7:  return 3.f*b*b*d; case 8:  return 6.f*b*c*d;
        case 9:  return 3.f*c*c*d; case 10: return a*a*a;     case 11: return 3.f*a*a*b;
        case 12: return 3.f*a*a*c; case 13: return 3.f*a*b*b; case 14: return 6.f*a*b*c;
        case 15: return 3.f*a*c*c; case 16: return b*b*b;     case 17: return 3.f*b*b*c;
        case 18: return 3.f*b*c*c; case 19: return c*c*c;
    }
    return 0.f;
}

// R[p][kb*128+jj] = sum_j coefP(kb, p%20)(col j) * Wg_kb[((p/20)*384 + j)*128 + jj]
__global__ void rbuild_k(const float* __restrict__ W1, const float* __restrict__ W2,
                         const float* __restrict__ W3, const float* __restrict__ Wi,
                         const float* __restrict__ bi) {
    int p  = blockIdx.x;           // 0..63
    int kb = blockIdx.y;           // 0..2
    int jj = threadIdx.x;          // 0..127
    if (p >= 60) { g_R[(size_t)p*F0D + kb*ND + jj] = 0.f; return; }
    __shared__ float sa[F0D], sb[F0D], sc_[F0D], sd[F0D];
    for (int j = jj; j < F0D; j += 128) {
        sa[j] = Wi[j]; sb[j] = Wi[F0D+j]; sc_[j] = Wi[2*F0D+j]; sd[j] = bi[j];
    }
    __syncthreads();
    int t = p / 20, pm = p % 20;
    const float* Wg = ((kb == 0) ? W1 : (kb == 1 ? W2 : W3)) + (size_t)t*F0D*ND + jj;
    float s0 = 0.f, s1 = 0.f, s2 = 0.f, s3 = 0.f;
    #pragma unroll 2
    for (int j = 0; j < F0D; j += 4) {
        s0 = fmaf(coefP(kb, pm, sa[j],   sb[j],   sc_[j],   sd[j]),   Wg[(size_t)j*ND],     s0);
        s1 = fmaf(coefP(kb, pm, sa[j+1], sb[j+1], sc_[j+1], sd[j+1]), Wg[(size_t)(j+1)*ND], s1);
        s2 = fmaf(coefP(kb, pm, sa[j+2], sb[j+2], sc_[j+2], sd[j+2]), Wg[(size_t)(j+2)*ND], s2);
        s3 = fmaf(coefP(kb, pm, sa[j+3], sb[j+3], sc_[j+3], sd[j+3]), Wg[(size_t)(j+3)*ND], s3);
    }
    g_R[(size_t)p*F0D + kb*ND + jj] = (s0 + s1) + (s2 + s3);
}

// ---------------- L propagation from RAW A: 4-row register blocking ----------------
// mode 0: Mt -> U[20:40] + LMt + deg ; mode 1: LMt -> U[40:60]
__global__ void __launch_bounds__(256) lprop_k(int mode) {
    __shared__ float Ms[20*NPTS];          // 40 KB
    int b = blockIdx.y;
    const float* src = (mode ? g_LMt : g_Mt) + (size_t)b*20*NPTS;
    for (int i = threadIdx.x; i < 20*NPTS; i += 256) Ms[i] = src[i];
    __syncthreads();
    float inv = 1.0f / __uint_as_float(g_amax_bits);
    int wid = threadIdx.x >> 5, lane = threadIdx.x & 31;
    #pragma unroll 1
    for (int g = 0; g < 2; g++) {
        int il0 = blockIdx.x*64 + wid*8 + g*4;             // 4 consecutive rows
        const float* A0 = g_L + ((size_t)b*NPTS + il0)*NPTS;
        float acc[4][20];
        float rs[4] = {0.f, 0.f, 0.f, 0.f};
        #pragma unroll
        for (int r = 0; r < 4; r++)
            #pragma unroll
            for (int c = 0; c < 20; c++) acc[r][c] = 0.f;
        #pragma unroll 2
        for (int t = 0; t < 16; t++) {
            int idx = lane + 32*t;
            float a0 = A0[idx];
            float a1 = A0[NPTS + idx];
            float a2 = A0[2*NPTS + idx];
            float a3 = A0[3*NPTS + idx];
            rs[0] += a0; rs[1] += a1; rs[2] += a2; rs[3] += a3;
            #pragma unroll
            for (int c = 0; c < 20; c++) {
                float ms = Ms[c*NPTS + idx];
                acc[0][c] = fmaf(a0, ms, acc[0][c]);
                acc[1][c] = fmaf(a1, ms, acc[1][c]);
                acc[2][c] = fmaf(a2, ms, acc[2][c]);
                acc[3][c] = fmaf(a3, ms, acc[3][c]);
            }
        }
        #pragma unroll
        for (int r = 0; r < 4; r++) {
            #pragma unroll
            for (int o = 16; o; o >>= 1) rs[r] += __shfl_xor_sync(0xffffffff, rs[r], o);
            #pragma unroll
            for (int c = 0; c < 20; c++) {
                float v = acc[r][c];
                #pragma unroll
                for (int o = 16; o; o >>= 1) v += __shfl_xor_sync(0xffffffff, v, o);
                acc[r][c] = v;
            }
        }
        if (lane < 4) {                        // lane r handles row il0+r (all values warp-uniform)
            int il = il0 + lane;
            float rsv = (lane == 0) ? rs[0] : (lane == 1) ? rs[1] : (lane == 2) ? rs[2] : rs[3];
            float deg;
            if (!mode) { deg = rsv * inv - 1.0f; g_deg[(size_t)b*NPTS + il] = deg; }
            else        deg = g_deg[(size_t)b*NPTS + il];
            float* u = g_U + ((size_t)b*NPTS + il)*64 + (mode ? 40 : 20);
            #pragma unroll
            for (int c = 0; c < 20; c++) {
                float av = (lane == 0) ? acc[0][c] : (lane == 1) ? acc[1][c]
                         : (lane == 2) ? acc[2][c] : acc[3][c];
                float o = deg * Ms[c*NPTS + il] - av * inv;
                u[c] = o;
                if (!mode) g_LMt[(size_t)b*20*NPTS + c*NPTS + il] = o;
            }
        }
    }
}

// ---------------- F1 = leaky(U@R + bg) + F0(inline) ; epilogue: BN partials ----------------
__global__ void __launch_bounds__(256) f1gemm_k(
    const float* __restrict__ bg1, const float* __restrict__ bg2, const float* __restrict__ bg3,
    const float* __restrict__ Wi,  const float* __restrict__ bi)
{
    int bm = blockIdx.x * 128;
    int kb = blockIdx.y;
    const float* bg = (kb == 0) ? bg1 : (kb == 1 ? bg2 : bg3);
    __shared__ float As[8][128], Bs[8][128];
    __shared__ float sWa[128], sWb[128], sWc[128], sbi[128], sx[128], sy[128], sz[128];
    __shared__ float redS[16][128], redQ[16][128];
    int t = threadIdx.x;
    if (t < 128) {
        int c = kb*128 + t;
        sWa[t] = Wi[c]; sWb[t] = Wi[F0D+c]; sWc[t] = Wi[2*F0D+c]; sbi[t] = bi[c];
        int r = bm + t;
        sx[t] = g_X[(size_t)r*3]; sy[t] = g_X[(size_t)r*3+1]; sz[t] = g_X[(size_t)r*3+2];
    }
    int arow = t >> 1, acol = (t & 1) * 4;
    int brow = t >> 5, bcol = (t & 31) * 4;
    int tx = t & 15, ty = t >> 4;
    float acc[8][8] = {};
    const float* Aptr = g_U + (size_t)(bm + arow) * 64 + acol;
    const float* Bptr = g_R + (size_t)brow * F0D + kb * ND + bcol;
    __syncthreads();
    for (int k0 = 0; k0 < 64; k0 += 8) {
        float4 av = *(const float4*)(Aptr + k0);
        float4 bv = *(const float4*)(Bptr + (size_t)k0 * F0D);
        As[acol+0][arow] = av.x; As[acol+1][arow] = av.y;
        As[acol+2][arow] = av.z; As[acol+3][arow] = av.w;
        *(float4*)&Bs[brow][bcol] = bv;
        __syncthreads();
        #pragma unroll
        for (int kk = 0; kk < 8; kk++) {
            float ra[8], rb[8];
            *(float4*)(ra)   = *(float4*)&As[kk][ty*4];
            *(float4*)(ra+4) = *(float4*)&As[kk][64 + ty*4];
            *(float4*)(rb)   = *(float4*)&Bs[kk][tx*4];
            *(float4*)(rb+4) = *(float4*)&Bs[kk][64 + tx*4];
            #pragma unroll
            for (int i = 0; i < 8; i++)
                #pragma unroll
                for (int j = 0; j < 8; j++) acc[i][j] = fmaf(ra[i], rb[j], acc[i][j]);
        }
        __syncthreads();
    }
    float cS[8] = {}, cQ[8] = {};
    #pragma unroll
    for (int i = 0; i < 8; i++) {
        int rloc = (i < 4) ? ty*4 + i : 64 + ty*4 + (i-4);
        int r = bm + rloc;
        #pragma unroll
        for (int jj = 0; jj < 8; jj++) {
            int cloc = (jj < 4) ? tx*4 + jj : 64 + tx*4 + (jj-4);
            float v = acc[i][jj] + bg[cloc];
            v = (v > 0.0f) ? v : 0.01f * v;
            v += fmaf(sx[rloc], sWa[cloc],
                 fmaf(sy[rloc], sWb[cloc],
                 fmaf(sz[rloc], sWc[cloc], sbi[cloc])));
            g_F1[(size_t)r * F0D + kb * ND + cloc] = v;
            cS[jj] += v; cQ[jj] += v * v;
        }
    }
    #pragma unroll
    for (int jj = 0; jj < 8; jj++) {
        int cloc = (jj < 4) ? tx*4 + jj : 64 + tx*4 + (jj-4);
        redS[ty][cloc] = cS[jj]; redQ[ty][cloc] = cQ[jj];
    }
    __syncthreads();
    if (t < 128) {
        float s = 0.f, q = 0.f;
        #pragma unroll
        for (int g = 0; g < 16; g++) { s += redS[g][t]; q += redQ[g][t]; }
        g_ps[(size_t)blockIdx.x * F0D + kb * ND + t] = s;
        g_pq[(size_t)blockIdx.x * F0D + kb * ND + t] = q;
    }
}

// ---------------- final GEMM with fused BN finalize in prologue ----------------
__global__ void __launch_bounds__(256) fgemm_k(
    const float* __restrict__ WF, const float* __restrict__ bF,
    const float* __restrict__ gamma, const float* __restrict__ beta,
    float* __restrict__ out)
{
    __shared__ float As[8][128], Bs[8][128];
    __shared__ float sSC[F0D], sSh[F0D], sCB[ND];
    int t = threadIdx.x;
    for (int c = t; c < F0D; c += 256) {
        float s0=0.f, s1=0.f, q0=0.f, q1=0.f;
        #pragma unroll 4
        for (int rb = 0; rb < 128; rb += 2) {
            s0 += g_ps[(size_t)rb*F0D + c];     q0 += g_pq[(size_t)rb*F0D + c];
            s1 += g_ps[(size_t)(rb+1)*F0D + c]; q1 += g_pq[(size_t)(rb+1)*F0D + c];
        }
        float s = s0 + s1, q = q0 + q1;
        float mu  = s * (1.0f / NN);
        float var = q * (1.0f / NN) - mu * mu;
        float sc  = gamma[c] * rsqrtf(var + 1e-5f);
        sSC[c] = sc; sSh[c] = beta[c] - mu * sc;
    }
    __syncthreads();
    if (t < ND) {
        float s0 = bF[t], s1 = 0.f, s2 = 0.f, s3 = 0.f;
        #pragma unroll 2
        for (int k = 0; k < F0D; k += 4) {
            s0 = fmaf(sSh[k],   WF[(size_t)k*ND + t],     s0);
            s1 = fmaf(sSh[k+1], WF[(size_t)(k+1)*ND + t], s1);
            s2 = fmaf(sSh[k+2], WF[(size_t)(k+2)*ND + t], s2);
            s3 = fmaf(sSh[k+3], WF[(size_t)(k+3)*ND + t], s3);
        }
        sCB[t] = (s0 + s1) + (s2 + s3);
    }
    __syncthreads();

    int bm = blockIdx.x * 128;
    int arow = t >> 1, acol = (t & 1) * 4;
    int brow = t >> 5, bcol = (t & 31) * 4;
    int tx = t & 15, ty = t >> 4;
    float acc[8][8] = {};
    const float* Aptr = g_F1 + (size_t)(bm + arow) * F0D + acol;
    for (int k0 = 0; k0 < F0D; k0 += 8) {
        float4 av = *(const float4*)(Aptr + k0);
        float4 sc = *(const float4*)&sSC[k0 + acol];
        av.x *= sc.x; av.y *= sc.y; av.z *= sc.z; av.w *= sc.w;
        float4 bv = *(const float4*)(WF + (size_t)(k0 + brow) * ND + bcol);
        As[acol+0][arow] = av.x; As[acol+1][arow] = av.y;
        As[acol+2][arow] = av.z; As[acol+3][arow] = av.w;
        *(float4*)&Bs[brow][bcol] = bv;
        __syncthreads();
        #pragma unroll
        for (int kk = 0; kk < 8; kk++) {
            float ra[8], rb[8];
            *(float4*)(ra)   = *(float4*)&As[kk][ty*4];
            *(float4*)(ra+4) = *(float4*)&As[kk][64 + ty*4];
            *(float4*)(rb)   = *(float4*)&Bs[kk][tx*4];
            *(float4*)(rb+4) = *(float4*)&Bs[kk][64 + tx*4];
            #pragma unroll
            for (int i = 0; i < 8; i++)
                #pragma unroll
                for (int j = 0; j < 8; j++) acc[i][j] = fmaf(ra[i], rb[j], acc[i][j]);
        }
        __syncthreads();
    }
    #pragma unroll
    for (int i = 0; i < 8; i++) {
        int r    = bm + ((i < 4) ? ty*4 + i : 64 + ty*4 + (i-4));
        int b    = r >> 9;
        int nloc = r & 511;
        float* orow = out + ((size_t)b * HROWS + 1 + nloc) * ND;
        float v4[8];
        #pragma unroll
        for (int jj = 0; jj < 8; jj++) {
            int c = (jj < 4) ? tx*4 + jj : 64 + tx*4 + (jj-4);
            float v = acc[i][jj] + sCB[c];
            v4[jj] = (v > 0.0f) ? v : 0.01f * v;
        }
        *(float4*)(orow + tx*4)      = *(float4*)&v4[0];
        *(float4*)(orow + 64 + tx*4) = *(float4*)&v4[4];
    }
}

// ---------------- depot row + per-batch mean, fused ----------------
__global__ void depmean_k(const float* __restrict__ depot, const float* __restrict__ Wd,
                          const float* __restrict__ bd, float* __restrict__ out) {
    int b = blockIdx.x, t = threadIdx.x;                   // 32 x 512
    __shared__ float sm[4][128];
    __shared__ float depv[128];
    if (t < 128) {
        float v = fmaf(depot[b*2+0], Wd[t], fmaf(depot[b*2+1], Wd[ND + t], bd[t]));
        out[(size_t)b * HROWS * ND + t] = v;
        depv[t] = v;
    }
    __syncthreads();
    int seg = t >> 7, ch = t & 127;
    const float* base = out + (size_t)b * HROWS * ND + ch;
    float s = 0.f;
    int r0 = seg*128 + 1, r1 = r0 + 128;
    for (int r = r0; r < r1; r++) s += base[(size_t)r * ND];
    sm[seg][ch] = s;
    __syncthreads();
    if (t < 128) {
        float tot = depv[t] + sm[0][t] + sm[1][t] + sm[2][t] + sm[3][t];
        out[(size_t)BATCH * HROWS * ND + (size_t)b * ND + t] = tot * (1.0f / HROWS);
    }
}

// ---------------- launch ----------------
extern "C" void kernel_launch(void* const* d_in, const int* in_sizes, int n_in,
                              void* d_out, int out_size) {
    const float* loc   = (const float*)d_in[0];
    const float* dl    = (const float*)d_in[1];
    const float* depot = (const float*)d_in[3];
    const float* Wi    = (const float*)d_in[4];
    const float* bi    = (const float*)d_in[5];
    const float* Wd    = (const float*)d_in[6];
    const float* bd    = (const float*)d_in[7];
    const float* Wg1   = (const float*)d_in[8];
    const float* bg1   = (const float*)d_in[9];
    const float* Wg2   = (const float*)d_in[10];
    const float* bg2   = (const float*)d_in[11];
    const float* Wg3   = (const float*)d_in[12];
    const float* bg3   = (const float*)d_in[13];
    const float* gamma = (const float*)d_in[14];
    const float* beta  = (const float*)d_in[15];
    const float* WF    = (const float*)d_in[16];
    const float* bF    = (const float*)d_in[17];
    float* out = (float*)d_out;

    init_k   <<<1, 64>>>();
    dlmax_k  <<<NN/256, 256>>>(dl);
    mono_k   <<<(NN+255)/256, 256>>>(loc, dl);
    a_k      <<<dim3(16, 16, BATCH), 256>>>();
    rbuild_k <<<dim3(64, 3), ND>>>(Wg1, Wg2, Wg3, Wi, bi);
    lprop_k  <<<dim3(8, BATCH), 256>>>(0);         // LM  (+ deg)
    lprop_k  <<<dim3(8, BATCH), 256>>>(1);         // LLM
    f1gemm_k <<<dim3(NN/128, 3), 256>>>(bg1, bg2, bg3, Wi, bi);
    fgemm_k  <<<NN/128, 256>>>(WF, bF, gamma, beta, out);
    depmean_k<<<BATCH, 512>>>(depot, Wd, bd, out);
}